// round 1
// baseline (speedup 1.0000x reference)
#include <cuda_runtime.h>
#include <math.h>

// Problem constants
#define BB 16
#define CC 512
#define NN 2304      // 48*48
#define II 64

// ---------------- scratch (static device globals; no allocation) ----------------
__device__ float g_q[(size_t)BB * II * NN];          //  9 MB
__device__ float g_k[(size_t)BB * II * NN];          //  9 MB
__device__ float g_v[(size_t)BB * CC * NN];          // 72 MB
__device__ float g_s[(size_t)BB * NN * NN];          // 324 MB (S, then P in place)

// ---------------- generic tiled SGEMM ----------------
// C[m,n] = sum_k A[m,k] * B[k,n]   (per batch, batch = blockIdx.z)
// AK: A stored row-major M x K (k contiguous, lda = K). Else stored K x M (m contiguous, ld = M).
// BK: B stored N x K (k contiguous, ld = K).        Else stored K x N (n contiguous, ld = N).
// EPI: out = gamma * acc + R  (residual add)
// Requirements: K % 16 == 0, N % 128 == 0. M may be ragged only in the AK path (guarded).
static const int TM = 128, TN = 128, TK = 16;

template<bool AK, bool BK, bool EPI>
__global__ __launch_bounds__(256, 2)
void gemm_k(const float* __restrict__ A, const float* __restrict__ Bm,
            float* __restrict__ Cm, int M, int N, int K,
            long long sA, long long sB, long long sC,
            const float* __restrict__ R, long long sR,
            const float* __restrict__ gamma_p)
{
    A  += sA * (long long)blockIdx.z;
    Bm += sB * (long long)blockIdx.z;
    Cm += sC * (long long)blockIdx.z;
    if (EPI) R += sR * (long long)blockIdx.z;

    __shared__ float As[TK][TM];
    __shared__ float Bs[TK][TN];

    const int tid = threadIdx.x;
    const int n0 = blockIdx.x * TN;
    const int m0 = blockIdx.y * TM;
    const int tx = tid & 15;        // 16 col groups
    const int ty = tid >> 4;        // 16 row groups

    float acc[8][8];
    #pragma unroll
    for (int i = 0; i < 8; i++)
        #pragma unroll
        for (int j = 0; j < 8; j++) acc[i][j] = 0.f;

    for (int k0 = 0; k0 < K; k0 += TK) {
        // ---- load A tile into As[k][m] ----
        if (AK) {
            const int row = tid >> 1;
            const int kc  = (tid & 1) * 8;
            const int m   = m0 + row;
            float4 v0 = make_float4(0.f, 0.f, 0.f, 0.f), v1 = v0;
            if (m < M) {
                const float* p = A + (long long)m * K + k0 + kc;
                v0 = *(const float4*)p;
                v1 = *(const float4*)(p + 4);
            }
            As[kc + 0][row] = v0.x; As[kc + 1][row] = v0.y;
            As[kc + 2][row] = v0.z; As[kc + 3][row] = v0.w;
            As[kc + 4][row] = v1.x; As[kc + 5][row] = v1.y;
            As[kc + 6][row] = v1.z; As[kc + 7][row] = v1.w;
        } else {
            const int kr = tid >> 4;
            const int mc = (tid & 15) * 8;
            const float* p = A + (long long)(k0 + kr) * M + m0 + mc;
            *(float4*)&As[kr][mc]     = *(const float4*)p;
            *(float4*)&As[kr][mc + 4] = *(const float4*)(p + 4);
        }
        // ---- load B tile into Bs[k][n] ----
        if (!BK) {
            const int kr = tid >> 4;
            const int nc = (tid & 15) * 8;
            const float* p = Bm + (long long)(k0 + kr) * N + n0 + nc;
            *(float4*)&Bs[kr][nc]     = *(const float4*)p;
            *(float4*)&Bs[kr][nc + 4] = *(const float4*)(p + 4);
        } else {
            const int row = tid >> 1;
            const int kc  = (tid & 1) * 8;
            const float* p = Bm + (long long)(n0 + row) * K + k0 + kc;
            float4 v0 = *(const float4*)p;
            float4 v1 = *(const float4*)(p + 4);
            Bs[kc + 0][row] = v0.x; Bs[kc + 1][row] = v0.y;
            Bs[kc + 2][row] = v0.z; Bs[kc + 3][row] = v0.w;
            Bs[kc + 4][row] = v1.x; Bs[kc + 5][row] = v1.y;
            Bs[kc + 6][row] = v1.z; Bs[kc + 7][row] = v1.w;
        }
        __syncthreads();

        #pragma unroll
        for (int kk = 0; kk < TK; kk++) {
            float a[8], b[8];
            *(float4*)(a)     = *(const float4*)&As[kk][ty * 8];
            *(float4*)(a + 4) = *(const float4*)&As[kk][ty * 8 + 4];
            *(float4*)(b)     = *(const float4*)&Bs[kk][tx * 8];
            *(float4*)(b + 4) = *(const float4*)&Bs[kk][tx * 8 + 4];
            #pragma unroll
            for (int i = 0; i < 8; i++)
                #pragma unroll
                for (int j = 0; j < 8; j++)
                    acc[i][j] = fmaf(a[i], b[j], acc[i][j]);
        }
        __syncthreads();
    }

    const float g = EPI ? *gamma_p : 0.f;
    #pragma unroll
    for (int i = 0; i < 8; i++) {
        const int m = m0 + ty * 8 + i;
        if (m < M) {
            float* dst = Cm + (long long)m * N + n0 + tx * 8;
            if (EPI) {
                const float* r = R + (long long)m * N + n0 + tx * 8;
                float4 r0 = *(const float4*)r;
                float4 r1 = *(const float4*)(r + 4);
                float4 o0, o1;
                o0.x = fmaf(g, acc[i][0], r0.x); o0.y = fmaf(g, acc[i][1], r0.y);
                o0.z = fmaf(g, acc[i][2], r0.z); o0.w = fmaf(g, acc[i][3], r0.w);
                o1.x = fmaf(g, acc[i][4], r1.x); o1.y = fmaf(g, acc[i][5], r1.y);
                o1.z = fmaf(g, acc[i][6], r1.z); o1.w = fmaf(g, acc[i][7], r1.w);
                *(float4*)dst       = o0;
                *(float4*)(dst + 4) = o1;
            } else {
                float4 o0 = make_float4(acc[i][0], acc[i][1], acc[i][2], acc[i][3]);
                float4 o1 = make_float4(acc[i][4], acc[i][5], acc[i][6], acc[i][7]);
                *(float4*)dst       = o0;
                *(float4*)(dst + 4) = o1;
            }
        }
    }
}

// ---------------- row softmax over 2304 columns, in place ----------------
// 2304 = 9 * 256 exactly: each thread caches 9 elements in registers.
__global__ __launch_bounds__(256)
void softmax_rows(float* __restrict__ S)
{
    __shared__ float red[8];
    float* p = S + (size_t)blockIdx.x * NN;
    const int tid  = threadIdx.x;
    const int lane = tid & 31;
    const int wid  = tid >> 5;

    float v[9];
    float m = -1e30f;
    #pragma unroll
    for (int j = 0; j < 9; j++) {
        v[j] = p[tid + 256 * j];
        m = fmaxf(m, v[j]);
    }
    #pragma unroll
    for (int o = 16; o; o >>= 1) m = fmaxf(m, __shfl_xor_sync(0xffffffffu, m, o));
    if (lane == 0) red[wid] = m;
    __syncthreads();
    m = red[0];
    #pragma unroll
    for (int i = 1; i < 8; i++) m = fmaxf(m, red[i]);
    __syncthreads();

    float s = 0.f;
    #pragma unroll
    for (int j = 0; j < 9; j++) {
        v[j] = expf(v[j] - m);
        s += v[j];
    }
    #pragma unroll
    for (int o = 16; o; o >>= 1) s += __shfl_xor_sync(0xffffffffu, s, o);
    if (lane == 0) red[wid] = s;
    __syncthreads();
    s = 0.f;
    #pragma unroll
    for (int i = 0; i < 8; i++) s += red[i];

    const float inv = 1.f / s;
    #pragma unroll
    for (int j = 0; j < 9; j++) p[tid + 256 * j] = v[j] * inv;
}

// ---------------- launch ----------------
extern "C" void kernel_launch(void* const* d_in, const int* in_sizes, int n_in,
                              void* d_out, int out_size)
{
    const float* x     = (const float*)d_in[0];   // (16,512,48,48)
    const float* Wq    = (const float*)d_in[1];   // (64,512)
    const float* Wk    = (const float*)d_in[2];   // (64,512)
    const float* Wv    = (const float*)d_in[3];   // (512,512)
    const float* gamma = (const float*)d_in[4];   // (1,)
    float* out = (float*)d_out;

    float *q, *k, *v, *s;
    cudaGetSymbolAddress((void**)&q, g_q);
    cudaGetSymbolAddress((void**)&k, g_k);
    cudaGetSymbolAddress((void**)&v, g_v);
    cudaGetSymbolAddress((void**)&s, g_s);

    const long long sX = (long long)CC * NN;   // per-batch x / v / out stride
    const long long sQ = (long long)II * NN;   // per-batch q / k stride
    const long long sS = (long long)NN * NN;   // per-batch S stride

    dim3 blk(256);

    // q = Wq @ x, k = Wk @ x   : M=64, N=2304, K=512 (M ragged in AK path, guarded)
    gemm_k<true, false, false><<<dim3(NN / TN, 1, BB), blk>>>(
        Wq, x, q, II, NN, CC, 0, sX, sQ, nullptr, 0, nullptr);
    gemm_k<true, false, false><<<dim3(NN / TN, 1, BB), blk>>>(
        Wk, x, k, II, NN, CC, 0, sX, sQ, nullptr, 0, nullptr);

    // v = Wv @ x : M=512, N=2304, K=512
    gemm_k<true, false, false><<<dim3(NN / TN, CC / TM, BB), blk>>>(
        Wv, x, v, CC, NN, CC, 0, sX, sX, nullptr, 0, nullptr);

    // S = q^T @ k : M=N=2304, K=64  (A = q stored K x M, B = k stored K x N)
    gemm_k<false, false, false><<<dim3(NN / TN, NN / TM, BB), blk>>>(
        q, k, s, NN, NN, II, sQ, sQ, sS, nullptr, 0, nullptr);

    // P = softmax_rows(S) in place
    softmax_rows<<<BB * NN, 256>>>(s);

    // out = gamma * (v @ P^T) + x : M=512, N=2304, K=2304 (B = P stored N x K)
    gemm_k<true, true, true><<<dim3(NN / TN, CC / TM, BB), blk>>>(
        v, s, out, CC, NN, NN, sX, sS, sX, x, sX, gamma);
}

// round 4
// speedup vs baseline: 1.6849x; 1.6849x over previous
#include <cuda_runtime.h>
#include <stdint.h>
#include <math.h>

// Problem constants
#define BB 16
#define CC 512
#define NN 2304      // 48*48
#define II 64

// ---------------- scratch (static device globals; no allocation) ----------------
__device__ float g_q[(size_t)BB * II * NN];          //  9 MB
__device__ float g_k[(size_t)BB * II * NN];          //  9 MB
__device__ float g_v[(size_t)BB * CC * NN];          // 72 MB
__device__ float g_s[(size_t)BB * NN * NN];          // 324 MB (S, then P in place)

// =====================================================================
// helpers
// =====================================================================
__device__ __forceinline__ uint32_t smem_u32(const void* p) {
    uint32_t a;
    asm("{ .reg .u64 t; cvta.to.shared.u64 t, %1; cvt.u32.u64 %0, t; }"
        : "=r"(a) : "l"(p));
    return a;
}

__device__ __forceinline__ void cp_async16(uint32_t saddr, const void* gptr) {
    asm volatile("cp.async.cg.shared.global [%0], [%1], 16;"
                 :: "r"(saddr), "l"(gptr) : "memory");
}
__device__ __forceinline__ void cp_commit() {
    asm volatile("cp.async.commit_group;" ::: "memory");
}
template<int N>
__device__ __forceinline__ void cp_wait() {
    asm volatile("cp.async.wait_group %0;" :: "n"(N) : "memory");
}

__device__ __forceinline__ uint32_t f2tf32(float f) {
    uint32_t u;
    asm("cvt.rna.tf32.f32 %0, %1;" : "=r"(u) : "f"(f));
    return u;
}

// D += A(16x8, row) * B(8x8, col); fp32 accumulate, tf32 operands
__device__ __forceinline__ void mma16888(float* d, const uint32_t* a, const uint32_t* b) {
    asm volatile(
        "mma.sync.aligned.m16n8k8.row.col.f32.tf32.tf32.f32 "
        "{%0,%1,%2,%3}, {%4,%5,%6,%7}, {%8,%9}, {%0,%1,%2,%3};"
        : "+f"(d[0]), "+f"(d[1]), "+f"(d[2]), "+f"(d[3])
        : "r"(a[0]), "r"(a[1]), "r"(a[2]), "r"(a[3]), "r"(b[0]), "r"(b[1]));
}

// =====================================================================
// O = gamma * (V @ P^T) + X via mma.sync tf32
// C[m,n] = sum_k V[m,k] * P[n,k]; both operands K-contiguous (NT / row.col)
// CTA tile 128x128, K chunks of 16, 4-stage cp.async ring.
// =====================================================================
#define OSTR 20                     // smem row stride (floats), conflict-free frags
#define OTILE (128 * OSTR)          // floats per operand tile
#define OSTAGE (2 * OTILE)          // A + B per stage
#define ONCH (NN / 16)              // 144 k-chunks
#define OV_SMEM (4 * OSTAGE * 4)    // bytes: 81920

__global__ __launch_bounds__(256, 2)
void ov_mma_kernel(const float* __restrict__ V, const float* __restrict__ P,
                   const float* __restrict__ X, float* __restrict__ O,
                   const float* __restrict__ gamma_p)
{
    extern __shared__ float sm[];

    const int tid = threadIdx.x;
    const long long bz = blockIdx.z;
    const float* Vb = V + bz * (long long)(CC * NN);
    const float* Pb = P + bz * (long long)(NN * NN);
    const float* Xb = X + bz * (long long)(CC * NN);
    float*       Ob = O + bz * (long long)(CC * NN);

    const int m0 = blockIdx.y * 128;
    const int n0 = blockIdx.x * 128;

    // ---- cp.async staging mapping: thread t -> row t>>1, 8-float half (t&1)*8
    const int lrow = tid >> 1;
    const int lc   = (tid & 1) * 8;
    const float* gA = Vb + (long long)(m0 + lrow) * NN + lc;
    const float* gB = Pb + (long long)(n0 + lrow) * NN + lc;
    const uint32_t sbase = smem_u32(sm);
    const uint32_t sA_st = sbase + (uint32_t)(lrow * OSTR + lc) * 4u;
    const uint32_t sB_st = sA_st + OTILE * 4u;

#define OV_ISSUE(c)                                                        \
    do {                                                                   \
        const uint32_t off_ = (uint32_t)((c) & 3) * (OSTAGE * 4u);         \
        const float* pa_ = gA + (c) * 16;                                  \
        const float* pb_ = gB + (c) * 16;                                  \
        cp_async16(sA_st + off_,      pa_);                                \
        cp_async16(sA_st + off_ + 16, pa_ + 4);                            \
        cp_async16(sB_st + off_,      pb_);                                \
        cp_async16(sB_st + off_ + 16, pb_ + 4);                            \
        cp_commit();                                                       \
    } while (0)

    OV_ISSUE(0); OV_ISSUE(1); OV_ISSUE(2);

    // ---- warp/fragment geometry
    const int wid  = tid >> 5, lane = tid & 31;
    const int wm   = (wid >> 2) * 64;    // warp m offset (2 rows of warps)
    const int wn   = (wid & 3) * 32;     // warp n offset (4 cols of warps)
    const int g4   = lane >> 2;          // groupID 0..7
    const int tg   = lane & 3;           // thread-in-group 0..3

    float acc[4][4][4];
    #pragma unroll
    for (int i = 0; i < 4; i++)
        #pragma unroll
        for (int j = 0; j < 4; j++)
            #pragma unroll
            for (int r = 0; r < 4; r++) acc[i][j][r] = 0.f;

    for (int c = 0; c < ONCH; c++) {
        if (c + 2 < ONCH)       cp_wait<2>();
        else if (c + 1 < ONCH)  cp_wait<1>();
        else                    cp_wait<0>();
        __syncthreads();

        if (c + 3 < ONCH) OV_ISSUE(c + 3);   // fills buf (c+3)&3 != c&3

        const float* A_ = sm + (c & 3) * OSTAGE;
        const float* B_ = A_ + OTILE;

        #pragma unroll
        for (int s = 0; s < 2; s++) {
            const int kk = s * 8 + tg;
            uint32_t a[4][4], b[4][2];
            #pragma unroll
            for (int mt = 0; mt < 4; mt++) {
                const int r0 = wm + mt * 16 + g4;
                a[mt][0] = f2tf32(A_[r0 * OSTR + kk]);
                a[mt][1] = f2tf32(A_[(r0 + 8) * OSTR + kk]);
                a[mt][2] = f2tf32(A_[r0 * OSTR + kk + 4]);
                a[mt][3] = f2tf32(A_[(r0 + 8) * OSTR + kk + 4]);
            }
            #pragma unroll
            for (int nt = 0; nt < 4; nt++) {
                const int nr = wn + nt * 8 + g4;
                b[nt][0] = f2tf32(B_[nr * OSTR + kk]);
                b[nt][1] = f2tf32(B_[nr * OSTR + kk + 4]);
            }
            #pragma unroll
            for (int mt = 0; mt < 4; mt++)
                #pragma unroll
                for (int nt = 0; nt < 4; nt++)
                    mma16888(acc[mt][nt], a[mt], b[nt]);
        }
    }

    // ---- epilogue: out = gamma*acc + X
    const float g = *gamma_p;
    #pragma unroll
    for (int mt = 0; mt < 4; mt++) {
        #pragma unroll
        for (int half = 0; half < 2; half++) {
            const int m = m0 + wm + mt * 16 + g4 + half * 8;
            const long long rb = (long long)m * NN;
            #pragma unroll
            for (int nt = 0; nt < 4; nt++) {
                const int n = n0 + wn + nt * 8 + 2 * tg;
                float2 xr = *(const float2*)(Xb + rb + n);
                float2 o;
                o.x = fmaf(g, acc[mt][nt][half * 2 + 0], xr.x);
                o.y = fmaf(g, acc[mt][nt][half * 2 + 1], xr.y);
                *(float2*)(Ob + rb + n) = o;
            }
        }
    }
#undef OV_ISSUE
}

// ---------------- generic tiled SGEMM (unchanged from round 1) ----------------
static const int TM = 128, TN = 128, TK = 16;

template<bool AK, bool BK, bool EPI>
__global__ __launch_bounds__(256, 2)
void gemm_k(const float* __restrict__ A, const float* __restrict__ Bm,
            float* __restrict__ Cm, int M, int N, int K,
            long long sA, long long sB, long long sC,
            const float* __restrict__ R, long long sR,
            const float* __restrict__ gamma_p)
{
    A  += sA * (long long)blockIdx.z;
    Bm += sB * (long long)blockIdx.z;
    Cm += sC * (long long)blockIdx.z;
    if (EPI) R += sR * (long long)blockIdx.z;

    __shared__ float As[TK][TM];
    __shared__ float Bs[TK][TN];

    const int tid = threadIdx.x;
    const int n0 = blockIdx.x * TN;
    const int m0 = blockIdx.y * TM;
    const int tx = tid & 15;
    const int ty = tid >> 4;

    float acc[8][8];
    #pragma unroll
    for (int i = 0; i < 8; i++)
        #pragma unroll
        for (int j = 0; j < 8; j++) acc[i][j] = 0.f;

    for (int k0 = 0; k0 < K; k0 += TK) {
        if (AK) {
            const int row = tid >> 1;
            const int kc  = (tid & 1) * 8;
            const int m   = m0 + row;
            float4 v0 = make_float4(0.f, 0.f, 0.f, 0.f), v1 = v0;
            if (m < M) {
                const float* p = A + (long long)m * K + k0 + kc;
                v0 = *(const float4*)p;
                v1 = *(const float4*)(p + 4);
            }
            As[kc + 0][row] = v0.x; As[kc + 1][row] = v0.y;
            As[kc + 2][row] = v0.z; As[kc + 3][row] = v0.w;
            As[kc + 4][row] = v1.x; As[kc + 5][row] = v1.y;
            As[kc + 6][row] = v1.z; As[kc + 7][row] = v1.w;
        } else {
            const int kr = tid >> 4;
            const int mc = (tid & 15) * 8;
            const float* p = A + (long long)(k0 + kr) * M + m0 + mc;
            *(float4*)&As[kr][mc]     = *(const float4*)p;
            *(float4*)&As[kr][mc + 4] = *(const float4*)(p + 4);
        }
        if (!BK) {
            const int kr = tid >> 4;
            const int nc = (tid & 15) * 8;
            const float* p = Bm + (long long)(k0 + kr) * N + n0 + nc;
            *(float4*)&Bs[kr][nc]     = *(const float4*)p;
            *(float4*)&Bs[kr][nc + 4] = *(const float4*)(p + 4);
        } else {
            const int row = tid >> 1;
            const int kc  = (tid & 1) * 8;
            const float* p = Bm + (long long)(n0 + row) * K + k0 + kc;
            float4 v0 = *(const float4*)p;
            float4 v1 = *(const float4*)(p + 4);
            Bs[kc + 0][row] = v0.x; Bs[kc + 1][row] = v0.y;
            Bs[kc + 2][row] = v0.z; Bs[kc + 3][row] = v0.w;
            Bs[kc + 4][row] = v1.x; Bs[kc + 5][row] = v1.y;
            Bs[kc + 6][row] = v1.z; Bs[kc + 7][row] = v1.w;
        }
        __syncthreads();

        #pragma unroll
        for (int kk = 0; kk < TK; kk++) {
            float a[8], b[8];
            *(float4*)(a)     = *(const float4*)&As[kk][ty * 8];
            *(float4*)(a + 4) = *(const float4*)&As[kk][ty * 8 + 4];
            *(float4*)(b)     = *(const float4*)&Bs[kk][tx * 8];
            *(float4*)(b + 4) = *(const float4*)&Bs[kk][tx * 8 + 4];
            #pragma unroll
            for (int i = 0; i < 8; i++)
                #pragma unroll
                for (int j = 0; j < 8; j++)
                    acc[i][j] = fmaf(a[i], b[j], acc[i][j]);
        }
        __syncthreads();
    }

    const float g = EPI ? *gamma_p : 0.f;
    #pragma unroll
    for (int i = 0; i < 8; i++) {
        const int m = m0 + ty * 8 + i;
        if (m < M) {
            float* dst = Cm + (long long)m * N + n0 + tx * 8;
            if (EPI) {
                const float* r = R + (long long)m * N + n0 + tx * 8;
                float4 r0 = *(const float4*)r;
                float4 r1 = *(const float4*)(r + 4);
                float4 o0, o1;
                o0.x = fmaf(g, acc[i][0], r0.x); o0.y = fmaf(g, acc[i][1], r0.y);
                o0.z = fmaf(g, acc[i][2], r0.z); o0.w = fmaf(g, acc[i][3], r0.w);
                o1.x = fmaf(g, acc[i][4], r1.x); o1.y = fmaf(g, acc[i][5], r1.y);
                o1.z = fmaf(g, acc[i][6], r1.z); o1.w = fmaf(g, acc[i][7], r1.w);
                *(float4*)dst       = o0;
                *(float4*)(dst + 4) = o1;
            } else {
                float4 o0 = make_float4(acc[i][0], acc[i][1], acc[i][2], acc[i][3]);
                float4 o1 = make_float4(acc[i][4], acc[i][5], acc[i][6], acc[i][7]);
                *(float4*)dst       = o0;
                *(float4*)(dst + 4) = o1;
            }
        }
    }
}

// ---------------- row softmax over 2304 columns, in place ----------------
__global__ __launch_bounds__(256)
void softmax_rows(float* __restrict__ S)
{
    __shared__ float red[8];
    float* p = S + (size_t)blockIdx.x * NN;
    const int tid  = threadIdx.x;
    const int lane = tid & 31;
    const int wid  = tid >> 5;

    float v[9];
    float m = -1e30f;
    #pragma unroll
    for (int j = 0; j < 9; j++) {
        v[j] = p[tid + 256 * j];
        m = fmaxf(m, v[j]);
    }
    #pragma unroll
    for (int o = 16; o; o >>= 1) m = fmaxf(m, __shfl_xor_sync(0xffffffffu, m, o));
    if (lane == 0) red[wid] = m;
    __syncthreads();
    m = red[0];
    #pragma unroll
    for (int i = 1; i < 8; i++) m = fmaxf(m, red[i]);
    __syncthreads();

    float s = 0.f;
    #pragma unroll
    for (int j = 0; j < 9; j++) {
        v[j] = expf(v[j] - m);
        s += v[j];
    }
    #pragma unroll
    for (int o = 16; o; o >>= 1) s += __shfl_xor_sync(0xffffffffu, s, o);
    if (lane == 0) red[wid] = s;
    __syncthreads();
    s = 0.f;
    #pragma unroll
    for (int i = 0; i < 8; i++) s += red[i];

    const float inv = 1.f / s;
    #pragma unroll
    for (int j = 0; j < 9; j++) p[tid + 256 * j] = v[j] * inv;
}

// ---------------- launch ----------------
extern "C" void kernel_launch(void* const* d_in, const int* in_sizes, int n_in,
                              void* d_out, int out_size)
{
    const float* x     = (const float*)d_in[0];   // (16,512,48,48)
    const float* Wq    = (const float*)d_in[1];   // (64,512)
    const float* Wk    = (const float*)d_in[2];   // (64,512)
    const float* Wv    = (const float*)d_in[3];   // (512,512)
    const float* gamma = (const float*)d_in[4];   // (1,)
    float* out = (float*)d_out;

    float *q, *k, *v, *s;
    cudaGetSymbolAddress((void**)&q, g_q);
    cudaGetSymbolAddress((void**)&k, g_k);
    cudaGetSymbolAddress((void**)&v, g_v);
    cudaGetSymbolAddress((void**)&s, g_s);

    const long long sX = (long long)CC * NN;
    const long long sQ = (long long)II * NN;
    const long long sS = (long long)NN * NN;

    dim3 blk(256);

    // q = Wq @ x, k = Wk @ x
    gemm_k<true, false, false><<<dim3(NN / TN, 1, BB), blk>>>(
        Wq, x, q, II, NN, CC, 0, sX, sQ, nullptr, 0, nullptr);
    gemm_k<true, false, false><<<dim3(NN / TN, 1, BB), blk>>>(
        Wk, x, k, II, NN, CC, 0, sX, sQ, nullptr, 0, nullptr);

    // v = Wv @ x
    gemm_k<true, false, false><<<dim3(NN / TN, CC / TM, BB), blk>>>(
        Wv, x, v, CC, NN, CC, 0, sX, sX, nullptr, 0, nullptr);

    // S = q^T @ k  (fp32 — logits must stay exact-ish)
    gemm_k<false, false, false><<<dim3(NN / TN, NN / TM, BB), blk>>>(
        q, k, s, NN, NN, II, sQ, sQ, sS, nullptr, 0, nullptr);

    // P = softmax_rows(S) in place
    softmax_rows<<<BB * NN, 256>>>(s);

    // out = gamma * (v @ P^T) + x  — tf32 mma.sync tensor cores
    cudaFuncSetAttribute(ov_mma_kernel,
                         cudaFuncAttributeMaxDynamicSharedMemorySize, OV_SMEM);
    ov_mma_kernel<<<dim3(NN / 128, CC / 128, BB), blk, OV_SMEM>>>(
        v, s, x, out, gamma);
}